// round 1
// baseline (speedup 1.0000x reference)
#include <cuda_runtime.h>
#include <cuda_bf16.h>

// Problem constants (match reference_code)
#define NN 50000
#define EE 800000
#define FIN 256
#define FOUT 64

// Scratch (no cudaMalloc allowed) — static __device__ globals.
__device__ float g_deg[NN];              // degree, then rsqrt(deg) in place
__device__ float g_h[NN * FOUT];         // h = x @ W
__device__ float g_acc[NN * FOUT];       // aggregation accumulator

// ---------------------------------------------------------------------------
// K1: deg init to 1.0 (self loop)
__global__ void k_init_deg() {
    int i = blockIdx.x * blockDim.x + threadIdx.x;
    if (i < NN) g_deg[i] = 1.0f;
}

// K2: deg accumulation over edge dst
__global__ void k_deg(const int* __restrict__ dst) {
    int e = blockIdx.x * blockDim.x + threadIdx.x;
    if (e < EE) atomicAdd(&g_deg[dst[e]], 1.0f);
}

// K3: dinv = rsqrt(deg) in place
__global__ void k_rsqrt() {
    int i = blockIdx.x * blockDim.x + threadIdx.x;
    if (i < NN) g_deg[i] = rsqrtf(g_deg[i]);
}

// ---------------------------------------------------------------------------
// K4: tiled GEMM h = x @ W, epilogue also writes acc = h * dinv^2 (self loop)
// Tile: BM=64 rows x FOUT=64 cols, BK=16. 256 threads, 4x4 register tile each.
#define BM 64
#define BK 16

__global__ __launch_bounds__(256, 4) void k_gemm(
    const float* __restrict__ x, const float* __restrict__ W)
{
    __shared__ float As[BK][BM + 4];   // x tile, transposed (stride 68: 16B-aligned rows of 4)
    __shared__ float Bs[BK][FOUT];     // W tile

    const int block_row = blockIdx.x * BM;
    const int t  = threadIdx.x;
    const int tx = t & 15;   // output col group (4 cols)
    const int ty = t >> 4;   // output row group (4 rows)

    // loader indices
    const int lr = t >> 2;          // 0..63: x row within tile
    const int lq = t & 3;           // 0..3 : x quad (4 floats)
    const int wr = t >> 4;          // 0..15: W k-row
    const int wq = t & 15;          // 0..15: W quad

    float c[4][4];
#pragma unroll
    for (int i = 0; i < 4; i++)
#pragma unroll
        for (int j = 0; j < 4; j++) c[i][j] = 0.0f;

    const int grow = block_row + lr;
    const bool row_ok = (grow < NN);

    for (int k0 = 0; k0 < FIN; k0 += BK) {
        float4 xa = make_float4(0.f, 0.f, 0.f, 0.f);
        if (row_ok)
            xa = *reinterpret_cast<const float4*>(x + grow * FIN + k0 + lq * 4);
        As[lq * 4 + 0][lr] = xa.x;
        As[lq * 4 + 1][lr] = xa.y;
        As[lq * 4 + 2][lr] = xa.z;
        As[lq * 4 + 3][lr] = xa.w;

        *reinterpret_cast<float4*>(&Bs[wr][wq * 4]) =
            *reinterpret_cast<const float4*>(W + (k0 + wr) * FOUT + wq * 4);

        __syncthreads();

#pragma unroll
        for (int kk = 0; kk < BK; kk++) {
            float4 a4 = *reinterpret_cast<const float4*>(&As[kk][ty * 4]);
            float4 b4 = *reinterpret_cast<const float4*>(&Bs[kk][tx * 4]);
            float a[4] = {a4.x, a4.y, a4.z, a4.w};
            float b[4] = {b4.x, b4.y, b4.z, b4.w};
#pragma unroll
            for (int i = 0; i < 4; i++)
#pragma unroll
                for (int j = 0; j < 4; j++)
                    c[i][j] = fmaf(a[i], b[j], c[i][j]);
        }
        __syncthreads();
    }

    // epilogue: h and acc(init with self-loop term)
#pragma unroll
    for (int i = 0; i < 4; i++) {
        int row = block_row + ty * 4 + i;
        if (row < NN) {
            float di = g_deg[row];       // dinv
            float sl = di * di;
            float4 hv = make_float4(c[i][0], c[i][1], c[i][2], c[i][3]);
            *reinterpret_cast<float4*>(&g_h[row * FOUT + tx * 4]) = hv;
            float4 av = make_float4(hv.x * sl, hv.y * sl, hv.z * sl, hv.w * sl);
            *reinterpret_cast<float4*>(&g_acc[row * FOUT + tx * 4]) = av;
        }
    }
}

// ---------------------------------------------------------------------------
// K5: edge scatter. 16 threads per edge, each handles a float4 (64 floats/row).
// Uses sm_90+ vector atomicAdd(float4*) -> 16B RED ops.
__global__ __launch_bounds__(256) void k_scatter(
    const int* __restrict__ src, const int* __restrict__ dst)
{
    int g = blockIdx.x * blockDim.x + threadIdx.x;
    int e = g >> 4;
    if (e >= EE) return;
    int lane = g & 15;

    int s = src[e];
    int d = dst[e];
    float nrm = g_deg[s] * g_deg[d];   // dinv[s]*dinv[d]

    float4 v = *reinterpret_cast<const float4*>(&g_h[s * FOUT + lane * 4]);
    v.x *= nrm; v.y *= nrm; v.z *= nrm; v.w *= nrm;

#if __CUDA_ARCH__ >= 900
    atomicAdd(reinterpret_cast<float4*>(&g_acc[d * FOUT + lane * 4]), v);
#else
    float* p = &g_acc[d * FOUT + lane * 4];
    atomicAdd(p + 0, v.x); atomicAdd(p + 1, v.y);
    atomicAdd(p + 2, v.z); atomicAdd(p + 3, v.w);
#endif
}

// ---------------------------------------------------------------------------
// K6: out = relu(acc + b)
__global__ void k_epilogue(const float* __restrict__ b, float* __restrict__ out)
{
    int i = blockIdx.x * blockDim.x + threadIdx.x;   // over N*FOUT/4 float4s
    if (i >= NN * FOUT / 4) return;
    float4 v  = reinterpret_cast<const float4*>(g_acc)[i];
    float4 bb = reinterpret_cast<const float4*>(b)[i & (FOUT / 4 - 1)];
    v.x = fmaxf(v.x + bb.x, 0.f);
    v.y = fmaxf(v.y + bb.y, 0.f);
    v.z = fmaxf(v.z + bb.z, 0.f);
    v.w = fmaxf(v.w + bb.w, 0.f);
    reinterpret_cast<float4*>(out)[i] = v;
}

// ---------------------------------------------------------------------------
extern "C" void kernel_launch(void* const* d_in, const int* in_sizes, int n_in,
                              void* d_out, int out_size)
{
    const float* x   = (const float*)d_in[0];   // [N, 256]
    const int*   adj = (const int*)d_in[1];     // [2, E]
    const float* W   = (const float*)d_in[2];   // [256, 64]
    const float* b   = (const float*)d_in[3];   // [64]
    float*       out = (float*)d_out;           // [N, 64]

    const int* src = adj;
    const int* dst = adj + EE;

    // degrees
    k_init_deg<<<(NN + 255) / 256, 256>>>();
    k_deg<<<(EE + 255) / 256, 256>>>(dst);
    k_rsqrt<<<(NN + 255) / 256, 256>>>();

    // GEMM + self-loop init of accumulator
    k_gemm<<<(NN + BM - 1) / BM, 256>>>(x, W);

    // edge aggregation
    long long total = (long long)EE * 16;
    k_scatter<<<(int)((total + 255) / 256), 256>>>(src, dst);

    // bias + relu
    k_epilogue<<<(NN * FOUT / 4 + 255) / 256, 256>>>(b, out);
}

// round 3
// speedup vs baseline: 1.1464x; 1.1464x over previous
#include <cuda_runtime.h>
#include <cuda_bf16.h>
#include <cstdint>

// Problem constants (match reference_code)
#define NN 50000
#define EE 800000
#define FIN 256
#define FOUT 64

// Scratch (no cudaMalloc allowed) — static __device__ globals.
__device__ float g_deg[NN];              // degree, then rsqrt(deg) in place
__device__ float g_h[NN * FOUT];         // h = x @ W
__device__ float g_acc[NN * FOUT];       // aggregation accumulator

// ---------------------------------------------------------------------------
// K1: deg init to 1.0 (self loop)
__global__ void k_init_deg() {
    int i = blockIdx.x * blockDim.x + threadIdx.x;
    if (i < NN) g_deg[i] = 1.0f;
}

// K2: deg accumulation over edge dst
__global__ void k_deg(const int* __restrict__ dst) {
    int e = blockIdx.x * blockDim.x + threadIdx.x;
    if (e < EE) atomicAdd(&g_deg[dst[e]], 1.0f);
}

// K3: dinv = rsqrt(deg) in place
__global__ void k_rsqrt() {
    int i = blockIdx.x * blockDim.x + threadIdx.x;
    if (i < NN) g_deg[i] = rsqrtf(g_deg[i]);
}

// ---------------------------------------------------------------------------
// K4: mma.sync bf16 GEMM  h = x @ W  with split-bf16:
//   x = x_hi + x_lo, W = W_hi + W_lo; h ≈ x_hi*W_hi + x_hi*W_lo + x_lo*W_hi
// CTA: 128 rows, 512 threads (16 warps: 8 m-stripes x 2 n-halves).
// A fragments straight from global fp32 x (converted in regs).
// W staged once per CTA in smem as bf16 hi/lo, [n][k] layout, padded stride.

#define PAD_K 264   // 256 + 8 pad: conflict-free b-frag LDS
#define B_HI_OFF 0
#define B_LO_OFF (64 * PAD_K)               // in ushort units
#define GEMM_SMEM (2 * 64 * PAD_K * 2)      // bytes = 67584

__device__ __forceinline__ uint32_t pack_bf16(float a, float b) {
    __nv_bfloat162 t = __floats2bfloat162_rn(a, b);
    return *reinterpret_cast<uint32_t*>(&t);
}

__device__ __forceinline__ void mma_bf16(float* c, const uint32_t* a, uint32_t b0, uint32_t b1) {
    asm volatile(
        "mma.sync.aligned.m16n8k16.row.col.f32.bf16.bf16.f32 "
        "{%0,%1,%2,%3}, {%4,%5,%6,%7}, {%8,%9}, {%0,%1,%2,%3};"
        : "+f"(c[0]), "+f"(c[1]), "+f"(c[2]), "+f"(c[3])
        : "r"(a[0]), "r"(a[1]), "r"(a[2]), "r"(a[3]), "r"(b0), "r"(b1));
}

__global__ __launch_bounds__(512, 2) void k_gemm_mma(
    const float* __restrict__ x, const float* __restrict__ W)
{
    extern __shared__ __align__(16) ushort Bs[];   // [2][64][PAD_K] bf16 bits

    const int t    = threadIdx.x;
    const int wid  = t >> 5;
    const int lane = t & 31;
    const int g    = lane >> 2;     // group id (0..7)
    const int tig  = lane & 3;      // thread in group

    // ---- stage W -> smem bf16 hi/lo, [n][k] layout ----
    // 256*64 = 16384 elems / 512 threads = 32 each
#pragma unroll 8
    for (int it = 0; it < 32; ++it) {
        int idx = t + it * 512;
        int k = idx >> 6;           // 0..255
        int n = idx & 63;           // 0..63
        float w = W[k * FOUT + n];
        __nv_bfloat16 hb = __float2bfloat16(w);
        float hf = __bfloat162float(hb);
        __nv_bfloat16 lb = __float2bfloat16(w - hf);
        Bs[B_HI_OFF + n * PAD_K + k] = __bfloat16_as_ushort(hb);
        Bs[B_LO_OFF + n * PAD_K + k] = __bfloat16_as_ushort(lb);
    }
    __syncthreads();

    // ---- warp tiling ----
    const int stripe = wid & 7;         // m-stripe (16 rows)
    const int nhalf  = wid >> 3;        // 0/1 -> n 0..31 / 32..63
    const int row0   = blockIdx.x * 128 + stripe * 16;

    const int row1 = row0 + g;
    const int row2 = row1 + 8;
    const bool v1 = (row1 < NN);
    const bool v2 = (row2 < NN);
    const float* xr1 = x + (size_t)row1 * FIN;
    const float* xr2 = x + (size_t)row2 * FIN;

    float acc[4][4];
#pragma unroll
    for (int i = 0; i < 4; ++i)
#pragma unroll
        for (int j = 0; j < 4; ++j) acc[i][j] = 0.0f;

    // ---- K loop: 16 steps of k16 ----
#pragma unroll 4
    for (int s = 0; s < 16; ++s) {
        const int kb = s * 16 + tig * 2;

        float2 p0 = v1 ? *reinterpret_cast<const float2*>(xr1 + kb)
                       : make_float2(0.f, 0.f);
        float2 p1 = v2 ? *reinterpret_cast<const float2*>(xr2 + kb)
                       : make_float2(0.f, 0.f);
        float2 p2 = v1 ? *reinterpret_cast<const float2*>(xr1 + kb + 8)
                       : make_float2(0.f, 0.f);
        float2 p3 = v2 ? *reinterpret_cast<const float2*>(xr2 + kb + 8)
                       : make_float2(0.f, 0.f);

        uint32_t a_hi[4], a_lo[4];
        {
            __nv_bfloat16 h;
            float hf, l;
            // p0
            h = __float2bfloat16(p0.x); hf = __bfloat162float(h); l = p0.x - hf;
            __nv_bfloat16 h2 = __float2bfloat16(p0.y); float hf2 = __bfloat162float(h2);
            a_hi[0] = (uint32_t)__bfloat16_as_ushort(h) | ((uint32_t)__bfloat16_as_ushort(h2) << 16);
            a_lo[0] = (uint32_t)__bfloat16_as_ushort(__float2bfloat16(l)) |
                      ((uint32_t)__bfloat16_as_ushort(__float2bfloat16(p0.y - hf2)) << 16);
            // p1
            h = __float2bfloat16(p1.x); hf = __bfloat162float(h); l = p1.x - hf;
            h2 = __float2bfloat16(p1.y); hf2 = __bfloat162float(h2);
            a_hi[1] = (uint32_t)__bfloat16_as_ushort(h) | ((uint32_t)__bfloat16_as_ushort(h2) << 16);
            a_lo[1] = (uint32_t)__bfloat16_as_ushort(__float2bfloat16(l)) |
                      ((uint32_t)__bfloat16_as_ushort(__float2bfloat16(p1.y - hf2)) << 16);
            // p2
            h = __float2bfloat16(p2.x); hf = __bfloat162float(h); l = p2.x - hf;
            h2 = __float2bfloat16(p2.y); hf2 = __bfloat162float(h2);
            a_hi[2] = (uint32_t)__bfloat16_as_ushort(h) | ((uint32_t)__bfloat16_as_ushort(h2) << 16);
            a_lo[2] = (uint32_t)__bfloat16_as_ushort(__float2bfloat16(l)) |
                      ((uint32_t)__bfloat16_as_ushort(__float2bfloat16(p2.y - hf2)) << 16);
            // p3
            h = __float2bfloat16(p3.x); hf = __bfloat162float(h); l = p3.x - hf;
            h2 = __float2bfloat16(p3.y); hf2 = __bfloat162float(h2);
            a_hi[3] = (uint32_t)__bfloat16_as_ushort(h) | ((uint32_t)__bfloat16_as_ushort(h2) << 16);
            a_lo[3] = (uint32_t)__bfloat16_as_ushort(__float2bfloat16(l)) |
                      ((uint32_t)__bfloat16_as_ushort(__float2bfloat16(p3.y - hf2)) << 16);
        }

#pragma unroll
        for (int nt = 0; nt < 4; ++nt) {
            int n = nhalf * 32 + nt * 8 + g;
            const ushort* bh = &Bs[B_HI_OFF + n * PAD_K + kb];
            const ushort* bl = &Bs[B_LO_OFF + n * PAD_K + kb];
            uint32_t bh0 = *reinterpret_cast<const uint32_t*>(bh);
            uint32_t bh1 = *reinterpret_cast<const uint32_t*>(bh + 8);
            uint32_t bl0 = *reinterpret_cast<const uint32_t*>(bl);
            uint32_t bl1 = *reinterpret_cast<const uint32_t*>(bl + 8);
            mma_bf16(acc[nt], a_hi, bh0, bh1);
            mma_bf16(acc[nt], a_hi, bl0, bl1);
            mma_bf16(acc[nt], a_lo, bh0, bh1);
        }
    }

    // ---- epilogue: write h and acc = h * dinv^2 (self-loop init) ----
    float sl1 = 0.f, sl2 = 0.f;
    if (v1) { float di = g_deg[row1]; sl1 = di * di; }
    if (v2) { float di = g_deg[row2]; sl2 = di * di; }

#pragma unroll
    for (int nt = 0; nt < 4; ++nt) {
        int c0 = nhalf * 32 + nt * 8 + tig * 2;
        if (v1) {
            float2 hv = make_float2(acc[nt][0], acc[nt][1]);
            *reinterpret_cast<float2*>(&g_h[(size_t)row1 * FOUT + c0]) = hv;
            *reinterpret_cast<float2*>(&g_acc[(size_t)row1 * FOUT + c0]) =
                make_float2(hv.x * sl1, hv.y * sl1);
        }
        if (v2) {
            float2 hv = make_float2(acc[nt][2], acc[nt][3]);
            *reinterpret_cast<float2*>(&g_h[(size_t)row2 * FOUT + c0]) = hv;
            *reinterpret_cast<float2*>(&g_acc[(size_t)row2 * FOUT + c0]) =
                make_float2(hv.x * sl2, hv.y * sl2);
        }
    }
}

// ---------------------------------------------------------------------------
// K5: edge scatter. 16 threads per edge, each handles a float4 (64 floats/row).
__global__ __launch_bounds__(256) void k_scatter(
    const int* __restrict__ src, const int* __restrict__ dst)
{
    int g = blockIdx.x * blockDim.x + threadIdx.x;
    int e = g >> 4;
    if (e >= EE) return;
    int lane = g & 15;

    int s = src[e];
    int d = dst[e];
    float nrm = g_deg[s] * g_deg[d];   // dinv[s]*dinv[d]

    float4 v = *reinterpret_cast<const float4*>(&g_h[s * FOUT + lane * 4]);
    v.x *= nrm; v.y *= nrm; v.z *= nrm; v.w *= nrm;

#if __CUDA_ARCH__ >= 900
    atomicAdd(reinterpret_cast<float4*>(&g_acc[d * FOUT + lane * 4]), v);
#else
    float* p = &g_acc[d * FOUT + lane * 4];
    atomicAdd(p + 0, v.x); atomicAdd(p + 1, v.y);
    atomicAdd(p + 2, v.z); atomicAdd(p + 3, v.w);
#endif
}

// ---------------------------------------------------------------------------
// K6: out = relu(acc + b)
__global__ void k_epilogue(const float* __restrict__ b, float* __restrict__ out)
{
    int i = blockIdx.x * blockDim.x + threadIdx.x;   // over N*FOUT/4 float4s
    if (i >= NN * FOUT / 4) return;
    float4 v  = reinterpret_cast<const float4*>(g_acc)[i];
    float4 bb = reinterpret_cast<const float4*>(b)[i & (FOUT / 4 - 1)];
    v.x = fmaxf(v.x + bb.x, 0.f);
    v.y = fmaxf(v.y + bb.y, 0.f);
    v.z = fmaxf(v.z + bb.z, 0.f);
    v.w = fmaxf(v.w + bb.w, 0.f);
    reinterpret_cast<float4*>(out)[i] = v;
}

// ---------------------------------------------------------------------------
extern "C" void kernel_launch(void* const* d_in, const int* in_sizes, int n_in,
                              void* d_out, int out_size)
{
    const float* x   = (const float*)d_in[0];   // [N, 256]
    const int*   adj = (const int*)d_in[1];     // [2, E]
    const float* W   = (const float*)d_in[2];   // [256, 64]
    const float* b   = (const float*)d_in[3];   // [64]
    float*       out = (float*)d_out;           // [N, 64]

    const int* src = adj;
    const int* dst = adj + EE;

    static bool attr_set = false;
    if (!attr_set) {
        cudaFuncSetAttribute(k_gemm_mma,
                             cudaFuncAttributeMaxDynamicSharedMemorySize, GEMM_SMEM);
        attr_set = true;
    }

    // degrees
    k_init_deg<<<(NN + 255) / 256, 256>>>();
    k_deg<<<(EE + 255) / 256, 256>>>(dst);
    k_rsqrt<<<(NN + 255) / 256, 256>>>();

    // GEMM (mma.sync bf16 split) + self-loop init of accumulator
    k_gemm_mma<<<(NN + 127) / 128, 512, GEMM_SMEM>>>(x, W);

    // edge aggregation
    long long total = (long long)EE * 16;
    k_scatter<<<(int)((total + 255) / 256), 256>>>(src, dst);

    // bias + relu
    k_epilogue<<<(NN * FOUT / 4 + 255) / 256, 256>>>(b, out);
}